// round 5
// baseline (speedup 1.0000x reference)
#include <cuda_runtime.h>
#include <math.h>
#include <stdint.h>

#define BB 2
#define NSEQ 2048
#define DD 1024
#define NH 16
#define HS 64
#define MM (BB*NSEQ)   // 4096 rows

// ---------------- scratch (allocation-free, __device__ globals) ----------------
__device__ float g_xn [MM*DD];
__device__ float g_qkv[MM*3*DD];
__device__ float g_oh [MM*DD];
__device__ float g_x1 [MM*DD];
__device__ float g_xn2[MM*DD];
__device__ float g_y  [MM*2*DD];
__device__ float g_wqkv[DD*3*DD];
__device__ float g_wout[DD*DD];
__device__ float g_w1  [DD*2*DD];
__device__ float g_w2  [2*DD*DD];

__device__ __forceinline__ float gelu_tanh(float x){
    float u = 0.7978845608028654f * (x + 0.044715f*x*x*x);
    float t = 1.0f - 2.0f/(__expf(2.0f*u)+1.0f);
    return 0.5f*x*(1.0f+t);
}

__device__ __forceinline__ float tf32r(float x){
    uint32_t r;
    asm volatile("cvt.rna.tf32.f32 %0, %1;" : "=r"(r) : "f"(x));
    return __uint_as_float(r);
}

__device__ __forceinline__ void cp_async16(void* smem, const void* gmem){
    unsigned s = (unsigned)__cvta_generic_to_shared(smem);
    asm volatile("cp.async.cg.shared.global [%0], [%1], 16;" :: "r"(s), "l"(gmem));
}
__device__ __forceinline__ void cp_commit(){ asm volatile("cp.async.commit_group;"); }
template<int N> __device__ __forceinline__ void cp_wait(){ asm volatile("cp.async.wait_group %0;" :: "n"(N)); }

__device__ __forceinline__ void mma_tf32(float c[4], uint32_t a0, uint32_t a1,
                                         uint32_t a2, uint32_t a3,
                                         uint32_t b0, uint32_t b1){
    asm volatile(
        "mma.sync.aligned.m16n8k8.row.col.f32.tf32.tf32.f32 "
        "{%0,%1,%2,%3},{%4,%5,%6,%7},{%8,%9},{%0,%1,%2,%3};"
        : "+f"(c[0]), "+f"(c[1]), "+f"(c[2]), "+f"(c[3])
        : "r"(a0), "r"(a1), "r"(a2), "r"(a3), "r"(b0), "r"(b1));
}

// ---------------- tf32 rounding pass (weights) ----------------
__global__ __launch_bounds__(256) void round_kernel(const float* __restrict__ in,
                                                    float* __restrict__ out, int n4)
{
    const int i = blockIdx.x*256 + threadIdx.x;
    if (i < n4){
        float4 v = ((const float4*)in)[i];
        v.x = tf32r(v.x); v.y = tf32r(v.y); v.z = tf32r(v.z); v.w = tf32r(v.w);
        ((float4*)out)[i] = v;
    }
}

// ---------------- LayerNorm ----------------
__global__ __launch_bounds__(256) void ln_kernel(const float* __restrict__ x,
        const float* __restrict__ sc, const float* __restrict__ bi,
        float* __restrict__ out)
{
    const int row = blockIdx.x;
    const int t = threadIdx.x;
    const float4 v = ((const float4*)(x + (size_t)row*DD))[t];
    float s  = v.x+v.y+v.z+v.w;
    float sq = v.x*v.x+v.y*v.y+v.z*v.z+v.w*v.w;
    #pragma unroll
    for (int o=16;o>0;o>>=1){
        s  += __shfl_xor_sync(0xffffffffu,s ,o);
        sq += __shfl_xor_sync(0xffffffffu,sq,o);
    }
    __shared__ float ss[8], sqs[8];
    const int warp=t>>5, lane=t&31;
    if (lane==0){ ss[warp]=s; sqs[warp]=sq; }
    __syncthreads();
    if (t==0){
        float a=0.f,b=0.f;
        #pragma unroll
        for(int i=0;i<8;i++){a+=ss[i]; b+=sqs[i];}
        ss[0]=a; sqs[0]=b;
    }
    __syncthreads();
    const float mean = ss[0]*(1.0f/DD);
    const float var  = sqs[0]*(1.0f/DD) - mean*mean;
    const float inv  = rsqrtf(var + 1e-6f);
    const float4 sc4 = ((const float4*)sc)[t];
    const float4 bi4 = ((const float4*)bi)[t];
    float4 o4;
    o4.x = tf32r((v.x-mean)*inv*sc4.x + bi4.x);
    o4.y = tf32r((v.y-mean)*inv*sc4.y + bi4.y);
    o4.z = tf32r((v.z-mean)*inv*sc4.z + bi4.z);
    o4.w = tf32r((v.w-mean)*inv*sc4.w + bi4.w);
    ((float4*)(out + (size_t)row*DD))[t] = o4;
}

// ---------------- TF32 tensor-core GEMM 128x128x32, 256 threads ----------------
// Single __syncthreads per k-tile; prefetch issued after barrier (WAR-safe),
// overlapping the 4 mma k-steps. A,B must be pre-rounded to tf32.
#define BK 32
#define ASTR 36
#define BSTR 136
template<int EPI>
__global__ __launch_bounds__(256,2) void tgemm_kernel(
    const float* __restrict__ A, const float* __restrict__ B,
    float* __restrict__ C, int M, int N, int K,
    const float* __restrict__ bias, const float* __restrict__ res)
{
    extern __shared__ float smg[];
    float (*As)[128][ASTR] = (float(*)[128][ASTR])smg;              // 2 stages
    float (*Bs)[BK][BSTR]  = (float(*)[BK][BSTR])(smg + 2*128*ASTR);

    const int tid  = threadIdx.x;
    const int lane = tid & 31;
    const int warp = tid >> 5;
    const int wm = warp >> 1;
    const int wn = warp & 1;
    const int mB = wm*32;
    const int nB = wn*64;
    const int bm = blockIdx.y*128;
    const int bn = blockIdx.x*128;

    // loaders: A 128x32 (2 thr/row, 16 floats each); B 32x128 (8 thr/row)
    const int arow = tid >> 1, acol = (tid & 1) << 4;
    const int brow = tid >> 3, bcol = (tid & 7) << 4;

    const float* Ag = A + (size_t)(bm + arow)*K + acol;
    const float* Bg = B + (size_t)brow*N + bn + bcol;

    const int nk = K >> 5;

    // prologue: stage 0
    #pragma unroll
    for (int i = 0; i < 4; i++) cp_async16(&As[0][arow][acol + i*4], Ag + i*4);
    #pragma unroll
    for (int i = 0; i < 4; i++) cp_async16(&Bs[0][brow][bcol + i*4], Bg + i*4);
    cp_commit();

    float acc[2][8][4] = {};
    const int g = lane >> 2;   // fragment row group
    const int c = lane & 3;    // fragment col group

    for (int kt = 0; kt < nk; kt++){
        const int cur = kt & 1;
        cp_wait<0>();
        __syncthreads();          // stage cur visible; all prior reads of nxt done

        if (kt + 1 < nk){
            const int nxt = cur ^ 1;
            const float* a = Ag + (kt+1)*BK;
            const float* b = Bg + (size_t)((kt+1)*BK)*N;
            #pragma unroll
            for (int i = 0; i < 4; i++) cp_async16(&As[nxt][arow][acol + i*4], a + i*4);
            #pragma unroll
            for (int i = 0; i < 4; i++) cp_async16(&Bs[nxt][brow][bcol + i*4], b + i*4);
            cp_commit();
        }

        #pragma unroll
        for (int kk = 0; kk < 4; kk++){
            const int kc = kk*8 + c;
            uint32_t af[2][4], bf[8][2];
            #pragma unroll
            for (int i = 0; i < 2; i++){
                const int r0 = mB + i*16 + g;
                af[i][0] = __float_as_uint(As[cur][r0    ][kc    ]);
                af[i][1] = __float_as_uint(As[cur][r0 + 8][kc    ]);
                af[i][2] = __float_as_uint(As[cur][r0    ][kc + 4]);
                af[i][3] = __float_as_uint(As[cur][r0 + 8][kc + 4]);
            }
            #pragma unroll
            for (int j = 0; j < 8; j++){
                const int n = nB + j*8 + g;
                bf[j][0] = __float_as_uint(Bs[cur][kc    ][n]);
                bf[j][1] = __float_as_uint(Bs[cur][kc + 4][n]);
            }
            #pragma unroll
            for (int i = 0; i < 2; i++)
                #pragma unroll
                for (int j = 0; j < 8; j++)
                    mma_tf32(acc[i][j], af[i][0], af[i][1], af[i][2], af[i][3],
                             bf[j][0], bf[j][1]);
        }
    }

    #pragma unroll
    for (int i = 0; i < 2; i++){
        const int row = bm + mB + i*16 + g;
        #pragma unroll
        for (int j = 0; j < 8; j++){
            const int col = bn + nB + j*8 + c*2;
            float v0 = acc[i][j][0], v1 = acc[i][j][1];
            float v2 = acc[i][j][2], v3 = acc[i][j][3];
            const size_t o0 = (size_t)row*N + col;
            const size_t o1 = (size_t)(row+8)*N + col;
            if (EPI == 0){
                v0 = tf32r(v0); v1 = tf32r(v1); v2 = tf32r(v2); v3 = tf32r(v3);
            } else if (EPI == 1){
                const float b0 = bias[col], b1 = bias[col+1];
                v0 += b0 + res[o0];   v1 += b1 + res[o0+1];
                v2 += b0 + res[o1];   v3 += b1 + res[o1+1];
            } else if (EPI == 2){
                const float b0 = bias[col], b1 = bias[col+1];
                v0 = tf32r(gelu_tanh(v0 + b0)); v1 = tf32r(gelu_tanh(v1 + b1));
                v2 = tf32r(gelu_tanh(v2 + b0)); v3 = tf32r(gelu_tanh(v3 + b1));
            }
            *(float2*)(C + o0) = make_float2(v0, v1);
            *(float2*)(C + o1) = make_float2(v2, v3);
        }
    }
}

// ---------------- Causal flash attention on tensor cores (tf32) ----------------
#define ATS 68
__global__ __launch_bounds__(128, 3) void attn_tc_kernel(const float* __restrict__ qkv,
                                                         float* __restrict__ oh)
{
    extern __shared__ float sm[];
    float* Qs = sm;
    float* KP = sm + 64*ATS;
    float* Vt = sm + 2*64*ATS;

    const int qt = gridDim.x - 1 - blockIdx.x;
    const int bh = blockIdx.y;
    const int b = bh >> 4;
    const int h = bh & 15;
    const int tid = threadIdx.x;
    const int lane = tid & 31;
    const int warp = tid >> 5;
    const int mB = warp * 16;
    const int g = lane >> 2;
    const int c = lane & 3;
    const size_t base = (size_t)b * NSEQ * (3*DD);
    const int hoff = h * HS;

    for (int i = tid; i < 64*16; i += 128){
        const int row = i >> 4, d4 = (i & 15) << 2;
        const float4 q4 = *(const float4*)(qkv + base + (size_t)(qt*64+row)*(3*DD) + hoff + d4);
        *(float4*)&Qs[row*ATS + d4] = q4;
    }
    __syncthreads();

    uint32_t qa[8][4];
    #pragma unroll
    for (int kk = 0; kk < 8; kk++){
        qa[kk][0] = __float_as_uint(Qs[(mB+g  )*ATS + kk*8 + c    ]);
        qa[kk][1] = __float_as_uint(Qs[(mB+g+8)*ATS + kk*8 + c    ]);
        qa[kk][2] = __float_as_uint(Qs[(mB+g  )*ATS + kk*8 + c + 4]);
        qa[kk][3] = __float_as_uint(Qs[(mB+g+8)*ATS + kk*8 + c + 4]);
    }

    float o[8][4] = {};
    float m0=-1e30f, m1=-1e30f, l0=0.f, l1=0.f;

    const int r0g = qt*64 + mB + g;
    const int r1g = r0g + 8;

    for (int jt = 0; jt <= qt; jt++){
        __syncthreads();
        for (int i = tid; i < 64*16; i += 128){
            const int row = i >> 4, d4 = (i & 15) << 2;
            const size_t roff = base + (size_t)(jt*64+row)*(3*DD) + hoff + d4;
            const float4 k4 = *(const float4*)(qkv + roff + DD);
            *(float4*)&KP[row*ATS + d4] = k4;
            const float4 v4 = *(const float4*)(qkv + roff + 2*DD);
            Vt[(d4+0)*ATS+row]=v4.x; Vt[(d4+1)*ATS+row]=v4.y;
            Vt[(d4+2)*ATS+row]=v4.z; Vt[(d4+3)*ATS+row]=v4.w;
        }
        __syncthreads();

        float s[8][4] = {};
        #pragma unroll
        for (int kk = 0; kk < 8; kk++){
            #pragma unroll
            for (int j = 0; j < 8; j++){
                const uint32_t b0 = __float_as_uint(KP[(j*8+g)*ATS + kk*8 + c    ]);
                const uint32_t b1 = __float_as_uint(KP[(j*8+g)*ATS + kk*8 + c + 4]);
                mma_tf32(s[j], qa[kk][0], qa[kk][1], qa[kk][2], qa[kk][3], b0, b1);
            }
        }
        __syncthreads();

        float rm0 = -1e30f, rm1 = -1e30f;
        #pragma unroll
        for (int j = 0; j < 8; j++){
            const int col = jt*64 + j*8 + 2*c;
            #pragma unroll
            for (int t2 = 0; t2 < 2; t2++){
                float v0 = s[j][t2]*0.125f;
                float v1 = s[j][2+t2]*0.125f;
                if (jt == qt){
                    if (col+t2 > r0g) v0 = -1e30f;
                    if (col+t2 > r1g) v1 = -1e30f;
                }
                s[j][t2] = v0;  s[j][2+t2] = v1;
                rm0 = fmaxf(rm0, v0); rm1 = fmaxf(rm1, v1);
            }
        }
        #pragma unroll
        for (int off = 1; off <= 2; off <<= 1){
            rm0 = fmaxf(rm0, __shfl_xor_sync(0xffffffffu, rm0, off));
            rm1 = fmaxf(rm1, __shfl_xor_sync(0xffffffffu, rm1, off));
        }
        const float mn0 = fmaxf(m0, rm0), mn1 = fmaxf(m1, rm1);
        const float alpha0 = __expf(m0 - mn0), alpha1 = __expf(m1 - mn1);
        m0 = mn0; m1 = mn1;

        float rs0 = 0.f, rs1 = 0.f;
        #pragma unroll
        for (int j = 0; j < 8; j++){
            float p0 = __expf(s[j][0] - mn0);
            float p1 = __expf(s[j][1] - mn0);
            float p2 = __expf(s[j][2] - mn1);
            float p3 = __expf(s[j][3] - mn1);
            rs0 += p0 + p1;  rs1 += p2 + p3;
            *(float2*)&KP[(mB+g  )*ATS + j*8 + 2*c] = make_float2(tf32r(p0), tf32r(p1));
            *(float2*)&KP[(mB+g+8)*ATS + j*8 + 2*c] = make_float2(tf32r(p2), tf32r(p3));
        }
        #pragma unroll
        for (int off = 1; off <= 2; off <<= 1){
            rs0 += __shfl_xor_sync(0xffffffffu, rs0, off);
            rs1 += __shfl_xor_sync(0xffffffffu, rs1, off);
        }
        l0 = l0*alpha0 + rs0;
        l1 = l1*alpha1 + rs1;

        #pragma unroll
        for (int j = 0; j < 8; j++){
            o[j][0] *= alpha0; o[j][1] *= alpha0;
            o[j][2] *= alpha1; o[j][3] *= alpha1;
        }
        __syncwarp();

        #pragma unroll
        for (int kk = 0; kk < 8; kk++){
            const uint32_t a0 = __float_as_uint(KP[(mB+g  )*ATS + kk*8 + c    ]);
            const uint32_t a1 = __float_as_uint(KP[(mB+g+8)*ATS + kk*8 + c    ]);
            const uint32_t a2 = __float_as_uint(KP[(mB+g  )*ATS + kk*8 + c + 4]);
            const uint32_t a3 = __float_as_uint(KP[(mB+g+8)*ATS + kk*8 + c + 4]);
            #pragma unroll
            for (int j = 0; j < 8; j++){
                const uint32_t b0 = __float_as_uint(Vt[(j*8+g)*ATS + kk*8 + c    ]);
                const uint32_t b1 = __float_as_uint(Vt[(j*8+g)*ATS + kk*8 + c + 4]);
                mma_tf32(o[j], a0, a1, a2, a3, b0, b1);
            }
        }
    }

    const float inv0 = 1.0f/l0, inv1 = 1.0f/l1;
    #pragma unroll
    for (int j = 0; j < 8; j++){
        const int col = hoff + j*8 + 2*c;
        float* p0 = oh + (size_t)(b*NSEQ + r0g)*DD + col;
        float* p1 = oh + (size_t)(b*NSEQ + r1g)*DD + col;
        *(float2*)p0 = make_float2(tf32r(o[j][0]*inv0), tf32r(o[j][1]*inv0));
        *(float2*)p1 = make_float2(tf32r(o[j][2]*inv1), tf32r(o[j][3]*inv1));
    }
}

// ---------------- launch ----------------
extern "C" void kernel_launch(void* const* d_in, const int* in_sizes, int n_in,
                              void* d_out, int out_size)
{
    const float* x    = (const float*)d_in[0];
    const float* ln1s = (const float*)d_in[1];
    const float* ln1b = (const float*)d_in[2];
    const float* wqkv = (const float*)d_in[3];
    const float* wout = (const float*)d_in[4];
    const float* bout = (const float*)d_in[5];
    const float* ln2s = (const float*)d_in[6];
    const float* ln2b = (const float*)d_in[7];
    const float* w1   = (const float*)d_in[8];
    const float* b1   = (const float*)d_in[9];
    const float* w2   = (const float*)d_in[10];
    const float* b2   = (const float*)d_in[11];
    float* out = (float*)d_out;

    float *p_xn,*p_qkv,*p_oh,*p_x1,*p_xn2,*p_y;
    float *p_wqkv,*p_wout,*p_w1,*p_w2;
    cudaGetSymbolAddress((void**)&p_xn , g_xn );
    cudaGetSymbolAddress((void**)&p_qkv, g_qkv);
    cudaGetSymbolAddress((void**)&p_oh , g_oh );
    cudaGetSymbolAddress((void**)&p_x1 , g_x1 );
    cudaGetSymbolAddress((void**)&p_xn2, g_xn2);
    cudaGetSymbolAddress((void**)&p_y  , g_y  );
    cudaGetSymbolAddress((void**)&p_wqkv, g_wqkv);
    cudaGetSymbolAddress((void**)&p_wout, g_wout);
    cudaGetSymbolAddress((void**)&p_w1  , g_w1  );
    cudaGetSymbolAddress((void**)&p_w2  , g_w2  );

    const int attn_smem = 3*64*ATS*sizeof(float);
    cudaFuncSetAttribute(attn_tc_kernel, cudaFuncAttributeMaxDynamicSharedMemorySize, attn_smem);
    const int gemm_smem = (2*128*ASTR + 2*BK*BSTR)*sizeof(float);   // 71680
    cudaFuncSetAttribute(tgemm_kernel<0>, cudaFuncAttributeMaxDynamicSharedMemorySize, gemm_smem);
    cudaFuncSetAttribute(tgemm_kernel<1>, cudaFuncAttributeMaxDynamicSharedMemorySize, gemm_smem);
    cudaFuncSetAttribute(tgemm_kernel<2>, cudaFuncAttributeMaxDynamicSharedMemorySize, gemm_smem);

    // round weights to tf32
    round_kernel<<<(DD*3*DD/4+255)/256,256>>>(wqkv, p_wqkv, DD*3*DD/4);
    round_kernel<<<(DD*DD/4+255)/256,256>>>(wout, p_wout, DD*DD/4);
    round_kernel<<<(DD*2*DD/4+255)/256,256>>>(w1, p_w1, DD*2*DD/4);
    round_kernel<<<(2*DD*DD/4+255)/256,256>>>(w2, p_w2, 2*DD*DD/4);

    ln_kernel<<<MM,256>>>(x, ln1s, ln1b, p_xn);
    tgemm_kernel<0><<<dim3(3*DD/128, MM/128),256,gemm_smem>>>(p_xn, p_wqkv, p_qkv, MM, 3*DD, DD, nullptr, nullptr);
    attn_tc_kernel<<<dim3(NSEQ/64, BB*NH),128,attn_smem>>>(p_qkv, p_oh);
    tgemm_kernel<1><<<dim3(DD/128, MM/128),256,gemm_smem>>>(p_oh, p_wout, p_x1, MM, DD, DD, bout, x);
    ln_kernel<<<MM,256>>>(p_x1, ln2s, ln2b, p_xn2);
    tgemm_kernel<2><<<dim3(2*DD/128, MM/128),256,gemm_smem>>>(p_xn2, p_w1, p_y, MM, 2*DD, DD, b1, nullptr);
    tgemm_kernel<1><<<dim3(DD/128, MM/128),256,gemm_smem>>>(p_y, p_w2, out, MM, DD, 2*DD, b2, p_x1);
}

// round 9
// speedup vs baseline: 1.2352x; 1.2352x over previous
#include <cuda_runtime.h>
#include <math.h>
#include <stdint.h>

#define BB 2
#define NSEQ 2048
#define DD 1024
#define NH 16
#define HS 64
#define MM (BB*NSEQ)   // 4096 rows

// ---------------- scratch (allocation-free, __device__ globals) ----------------
__device__ float g_xn [MM*DD];
__device__ float g_qkv[MM*3*DD];
__device__ float g_oh [MM*DD];
__device__ float g_x1 [MM*DD];
__device__ float g_xn2[MM*DD];
__device__ float g_y  [MM*2*DD];
__device__ float g_wqkv[DD*3*DD];
__device__ float g_wout[DD*DD];
__device__ float g_w1  [DD*2*DD];
__device__ float g_w2  [2*DD*DD];

__device__ __forceinline__ float gelu_tanh(float x){
    float u = 0.7978845608028654f * (x + 0.044715f*x*x*x);
    float t = 1.0f - 2.0f/(__expf(2.0f*u)+1.0f);
    return 0.5f*x*(1.0f+t);
}

__device__ __forceinline__ float tf32r(float x){
    uint32_t r;
    asm volatile("cvt.rna.tf32.f32 %0, %1;" : "=r"(r) : "f"(x));
    return __uint_as_float(r);
}

__device__ __forceinline__ void cp_async16(void* smem, const void* gmem){
    unsigned s = (unsigned)__cvta_generic_to_shared(smem);
    asm volatile("cp.async.cg.shared.global [%0], [%1], 16;" :: "r"(s), "l"(gmem));
}
__device__ __forceinline__ void cp_commit(){ asm volatile("cp.async.commit_group;"); }
template<int N> __device__ __forceinline__ void cp_wait(){ asm volatile("cp.async.wait_group %0;" :: "n"(N)); }

__device__ __forceinline__ void mma_tf32(float c[4], uint32_t a0, uint32_t a1,
                                         uint32_t a2, uint32_t a3,
                                         uint32_t b0, uint32_t b1){
    asm volatile(
        "mma.sync.aligned.m16n8k8.row.col.f32.tf32.tf32.f32 "
        "{%0,%1,%2,%3},{%4,%5,%6,%7},{%8,%9},{%0,%1,%2,%3};"
        : "+f"(c[0]), "+f"(c[1]), "+f"(c[2]), "+f"(c[3])
        : "r"(a0), "r"(a1), "r"(a2), "r"(a3), "r"(b0), "r"(b1));
}

// ---------------- tf32 rounding pass (weights) ----------------
__global__ __launch_bounds__(256) void round_kernel(const float* __restrict__ in,
                                                    float* __restrict__ out, int n4)
{
    const int i = blockIdx.x*256 + threadIdx.x;
    if (i < n4){
        float4 v = ((const float4*)in)[i];
        v.x = tf32r(v.x); v.y = tf32r(v.y); v.z = tf32r(v.z); v.w = tf32r(v.w);
        ((float4*)out)[i] = v;
    }
}

// ---------------- LayerNorm: one block per row, output tf32-rounded ----------------
__global__ __launch_bounds__(256) void ln_kernel(const float* __restrict__ x,
        const float* __restrict__ sc, const float* __restrict__ bi,
        float* __restrict__ out)
{
    const int row = blockIdx.x;
    const int t = threadIdx.x;
    const float4 v = ((const float4*)(x + (size_t)row*DD))[t];
    float s  = v.x+v.y+v.z+v.w;
    float sq = v.x*v.x+v.y*v.y+v.z*v.z+v.w*v.w;
    #pragma unroll
    for (int o=16;o>0;o>>=1){
        s  += __shfl_xor_sync(0xffffffffu,s ,o);
        sq += __shfl_xor_sync(0xffffffffu,sq,o);
    }
    __shared__ float ss[8], sqs[8];
    const int warp=t>>5, lane=t&31;
    if (lane==0){ ss[warp]=s; sqs[warp]=sq; }
    __syncthreads();
    if (t==0){
        float a=0.f,b=0.f;
        #pragma unroll
        for(int i=0;i<8;i++){a+=ss[i]; b+=sqs[i];}
        ss[0]=a; sqs[0]=b;
    }
    __syncthreads();
    const float mean = ss[0]*(1.0f/DD);
    const float var  = sqs[0]*(1.0f/DD) - mean*mean;
    const float inv  = rsqrtf(var + 1e-6f);
    const float4 sc4 = ((const float4*)sc)[t];
    const float4 bi4 = ((const float4*)bi)[t];
    float4 o4;
    o4.x = tf32r((v.x-mean)*inv*sc4.x + bi4.x);
    o4.y = tf32r((v.y-mean)*inv*sc4.y + bi4.y);
    o4.z = tf32r((v.z-mean)*inv*sc4.z + bi4.z);
    o4.w = tf32r((v.w-mean)*inv*sc4.w + bi4.w);
    ((float4*)(out + (size_t)row*DD))[t] = o4;
}

// ---------------- TF32 tensor-core GEMM 128x128x16, 3-stage pipeline ----------------
// One __syncthreads per k-tile:  wait<1> -> sync -> prefetch(kt+2) -> compute(kt).
// Stage (kt+2)%3 was last read at iteration kt-1; the barrier proves those reads done.
#define AS_STRIDE 20
#define BS_STRIDE 136
#define NSTG 3
template<int EPI>
__global__ __launch_bounds__(256) void tgemm_kernel(
    const float* __restrict__ A, const float* __restrict__ B,
    float* __restrict__ C, int M, int N, int K,
    const float* __restrict__ bias, const float* __restrict__ res)
{
    extern __shared__ float smg[];
    float (*As)[128][AS_STRIDE] = (float(*)[128][AS_STRIDE])smg;               // 3 stages
    float (*Bs)[16][BS_STRIDE]  = (float(*)[16][BS_STRIDE])(smg + NSTG*128*AS_STRIDE);

    const int tid  = threadIdx.x;
    const int lane = tid & 31;
    const int warp = tid >> 5;
    const int wm = warp >> 1;
    const int wn = warp & 1;
    const int mB = wm*32;
    const int nB = wn*64;
    const int bm = blockIdx.y*128;
    const int bn = blockIdx.x*128;

    const int ar  = tid >> 2;        // 0..63
    const int ac4 = (tid & 3) << 2;  // 0,4,8,12
    const int br  = tid >> 5;        // 0..7
    const int bc4 = (tid & 31) << 2; // 0..124

    const float* Ag0 = A + (size_t)(bm + ar     )*K + ac4;
    const float* Ag1 = A + (size_t)(bm + ar + 64)*K + ac4;
    const float* Bg0 = B + (size_t)(br    )*N + bn + bc4;
    const float* Bg1 = B + (size_t)(br + 8)*N + bn + bc4;

    const int nk = K >> 4;

    // prologue: stages 0 and 1
    #pragma unroll
    for (int p = 0; p < 2; p++){
        const int ko = p << 4;
        cp_async16(&As[p][ar     ][ac4], Ag0 + ko);
        cp_async16(&As[p][ar + 64][ac4], Ag1 + ko);
        cp_async16(&Bs[p][br    ][bc4], Bg0 + (size_t)ko*N);
        cp_async16(&Bs[p][br + 8][bc4], Bg1 + (size_t)ko*N);
        cp_commit();
    }

    float acc[2][8][4] = {};
    const int frow = lane >> 2;
    const int fcol = lane & 3;

    int cur = 0;
    for (int kt = 0; kt < nk; kt++){
        cp_wait<1>();            // stage kt landed (FIFO); kt+1 may still be in flight
        __syncthreads();         // all warps done reading stage (kt+2)%3 (read at kt-1)

        if (kt + 2 < nk){
            int nxt = cur + 2;                    // (cur+2) % NSTG — fixed
            if (nxt >= NSTG) nxt -= NSTG;
            const int ko = (kt+2) << 4;
            cp_async16(&As[nxt][ar     ][ac4], Ag0 + ko);
            cp_async16(&As[nxt][ar + 64][ac4], Ag1 + ko);
            cp_async16(&Bs[nxt][br    ][bc4], Bg0 + (size_t)ko*N);
            cp_async16(&Bs[nxt][br + 8][bc4], Bg1 + (size_t)ko*N);
            cp_commit();
        }

        #pragma unroll
        for (int kk = 0; kk < 2; kk++){
            const int kc = kk*8 + fcol;
            uint32_t af[2][4], bf[8][2];
            #pragma unroll
            for (int i = 0; i < 2; i++){
                const int r0 = mB + i*16 + frow;
                af[i][0] = __float_as_uint(As[cur][r0    ][kc    ]);
                af[i][1] = __float_as_uint(As[cur][r0 + 8][kc    ]);
                af[i][2] = __float_as_uint(As[cur][r0    ][kc + 4]);
                af[i][3] = __float_as_uint(As[cur][r0 + 8][kc + 4]);
            }
            #pragma unroll
            for (int j = 0; j < 8; j++){
                const int n = nB + j*8 + frow;
                bf[j][0] = __float_as_uint(Bs[cur][kk*8 + fcol    ][n]);
                bf[j][1] = __float_as_uint(Bs[cur][kk*8 + fcol + 4][n]);
            }
            #pragma unroll
            for (int i = 0; i < 2; i++)
                #pragma unroll
                for (int j = 0; j < 8; j++)
                    mma_tf32(acc[i][j], af[i][0], af[i][1], af[i][2], af[i][3],
                             bf[j][0], bf[j][1]);
        }
        cur = (cur + 1 == NSTG) ? 0 : cur + 1;
    }

    #pragma unroll
    for (int i = 0; i < 2; i++){
        const int row = bm + mB + i*16 + frow;
        #pragma unroll
        for (int j = 0; j < 8; j++){
            const int col = bn + nB + j*8 + fcol*2;
            float v0 = acc[i][j][0], v1 = acc[i][j][1];
            float v2 = acc[i][j][2], v3 = acc[i][j][3];
            const size_t o0 = (size_t)row*N + col;
            const size_t o1 = (size_t)(row+8)*N + col;
            if (EPI == 0){
                v0 = tf32r(v0); v1 = tf32r(v1); v2 = tf32r(v2); v3 = tf32r(v3);
            } else if (EPI == 1){
                const float b0 = bias[col], b1 = bias[col+1];
                v0 += b0 + res[o0];   v1 += b1 + res[o0+1];
                v2 += b0 + res[o1];   v3 += b1 + res[o1+1];
            } else if (EPI == 2){
                const float b0 = bias[col], b1 = bias[col+1];
                v0 = tf32r(gelu_tanh(v0 + b0)); v1 = tf32r(gelu_tanh(v1 + b1));
                v2 = tf32r(gelu_tanh(v2 + b0)); v3 = tf32r(gelu_tanh(v3 + b1));
            }
            *(float2*)(C + o0) = make_float2(v0, v1);
            *(float2*)(C + o1) = make_float2(v2, v3);
        }
    }
}

// ---------------- Causal flash attention on tensor cores (tf32) ----------------
#define ATS 68
__global__ __launch_bounds__(128, 3) void attn_tc_kernel(const float* __restrict__ qkv,
                                                         float* __restrict__ oh)
{
    extern __shared__ float sm[];
    float* Qs = sm;
    float* KP = sm + 64*ATS;
    float* Vt = sm + 2*64*ATS;

    const int qt = gridDim.x - 1 - blockIdx.x;
    const int bh = blockIdx.y;
    const int b = bh >> 4;
    const int h = bh & 15;
    const int tid = threadIdx.x;
    const int lane = tid & 31;
    const int warp = tid >> 5;
    const int mB = warp * 16;
    const int g = lane >> 2;
    const int c = lane & 3;
    const size_t base = (size_t)b * NSEQ * (3*DD);
    const int hoff = h * HS;

    for (int i = tid; i < 64*16; i += 128){
        const int row = i >> 4, d4 = (i & 15) << 2;
        const float4 q4 = *(const float4*)(qkv + base + (size_t)(qt*64+row)*(3*DD) + hoff + d4);
        *(float4*)&Qs[row*ATS + d4] = q4;
    }
    __syncthreads();

    uint32_t qa[8][4];
    #pragma unroll
    for (int kk = 0; kk < 8; kk++){
        qa[kk][0] = __float_as_uint(Qs[(mB+g  )*ATS + kk*8 + c    ]);
        qa[kk][1] = __float_as_uint(Qs[(mB+g+8)*ATS + kk*8 + c    ]);
        qa[kk][2] = __float_as_uint(Qs[(mB+g  )*ATS + kk*8 + c + 4]);
        qa[kk][3] = __float_as_uint(Qs[(mB+g+8)*ATS + kk*8 + c + 4]);
    }

    float o[8][4] = {};
    float m0=-1e30f, m1=-1e30f, l0=0.f, l1=0.f;

    const int r0g = qt*64 + mB + g;
    const int r1g = r0g + 8;

    for (int jt = 0; jt <= qt; jt++){
        __syncthreads();
        for (int i = tid; i < 64*16; i += 128){
            const int row = i >> 4, d4 = (i & 15) << 2;
            const size_t roff = base + (size_t)(jt*64+row)*(3*DD) + hoff + d4;
            const float4 k4 = *(const float4*)(qkv + roff + DD);
            *(float4*)&KP[row*ATS + d4] = k4;
            const float4 v4 = *(const float4*)(qkv + roff + 2*DD);
            Vt[(d4+0)*ATS+row]=v4.x; Vt[(d4+1)*ATS+row]=v4.y;
            Vt[(d4+2)*ATS+row]=v4.z; Vt[(d4+3)*ATS+row]=v4.w;
        }
        __syncthreads();

        float s[8][4] = {};
        #pragma unroll
        for (int kk = 0; kk < 8; kk++){
            #pragma unroll
            for (int j = 0; j < 8; j++){
                const uint32_t b0 = __float_as_uint(KP[(j*8+g)*ATS + kk*8 + c    ]);
                const uint32_t b1 = __float_as_uint(KP[(j*8+g)*ATS + kk*8 + c + 4]);
                mma_tf32(s[j], qa[kk][0], qa[kk][1], qa[kk][2], qa[kk][3], b0, b1);
            }
        }
        __syncthreads();

        float rm0 = -1e30f, rm1 = -1e30f;
        #pragma unroll
        for (int j = 0; j < 8; j++){
            const int col = jt*64 + j*8 + 2*c;
            #pragma unroll
            for (int t2 = 0; t2 < 2; t2++){
                float v0 = s[j][t2]*0.125f;
                float v1 = s[j][2+t2]*0.125f;
                if (jt == qt){
                    if (col+t2 > r0g) v0 = -1e30f;
                    if (col+t2 > r1g) v1 = -1e30f;
                }
                s[j][t2] = v0;  s[j][2+t2] = v1;
                rm0 = fmaxf(rm0, v0); rm1 = fmaxf(rm1, v1);
            }
        }
        #pragma unroll
        for (int off = 1; off <= 2; off <<= 1){
            rm0 = fmaxf(rm0, __shfl_xor_sync(0xffffffffu, rm0, off));
            rm1 = fmaxf(rm1, __shfl_xor_sync(0xffffffffu, rm1, off));
        }
        const float mn0 = fmaxf(m0, rm0), mn1 = fmaxf(m1, rm1);
        const float alpha0 = __expf(m0 - mn0), alpha1 = __expf(m1 - mn1);
        m0 = mn0; m1 = mn1;

        float rs0 = 0.f, rs1 = 0.f;
        #pragma unroll
        for (int j = 0; j < 8; j++){
            float p0 = __expf(s[j][0] - mn0);
            float p1 = __expf(s[j][1] - mn0);
            float p2 = __expf(s[j][2] - mn1);
            float p3 = __expf(s[j][3] - mn1);
            rs0 += p0 + p1;  rs1 += p2 + p3;
            *(float2*)&KP[(mB+g  )*ATS + j*8 + 2*c] = make_float2(tf32r(p0), tf32r(p1));
            *(float2*)&KP[(mB+g+8)*ATS + j*8 + 2*c] = make_float2(tf32r(p2), tf32r(p3));
        }
        #pragma unroll
        for (int off = 1; off <= 2; off <<= 1){
            rs0 += __shfl_xor_sync(0xffffffffu, rs0, off);
            rs1 += __shfl_xor_sync(0xffffffffu, rs1, off);
        }
        l0 = l0*alpha0 + rs0;
        l1 = l1*alpha1 + rs1;

        #pragma unroll
        for (int j = 0; j < 8; j++){
            o[j][0] *= alpha0; o[j][1] *= alpha0;
            o[j][2] *= alpha1; o[j][3] *= alpha1;
        }
        __syncwarp();

        #pragma unroll
        for (int kk = 0; kk < 8; kk++){
            const uint32_t a0 = __float_as_uint(KP[(mB+g  )*ATS + kk*8 + c    ]);
            const uint32_t a1 = __float_as_uint(KP[(mB+g+8)*ATS + kk*8 + c    ]);
            const uint32_t a2 = __float_as_uint(KP[(mB+g  )*ATS + kk*8 + c + 4]);
            const uint32_t a3 = __float_as_uint(KP[(mB+g+8)*ATS + kk*8 + c + 4]);
            #pragma unroll
            for (int j = 0; j < 8; j++){
                const uint32_t b0 = __float_as_uint(Vt[(j*8+g)*ATS + kk*8 + c    ]);
                const uint32_t b1 = __float_as_uint(Vt[(j*8+g)*ATS + kk*8 + c + 4]);
                mma_tf32(o[j], a0, a1, a2, a3, b0, b1);
            }
        }
    }

    const float inv0 = 1.0f/l0, inv1 = 1.0f/l1;
    #pragma unroll
    for (int j = 0; j < 8; j++){
        const int col = hoff + j*8 + 2*c;
        float* p0 = oh + (size_t)(b*NSEQ + r0g)*DD + col;
        float* p1 = oh + (size_t)(b*NSEQ + r1g)*DD + col;
        *(float2*)p0 = make_float2(tf32r(o[j][0]*inv0), tf32r(o[j][1]*inv0));
        *(float2*)p1 = make_float2(tf32r(o[j][2]*inv1), tf32r(o[j][3]*inv1));
    }
}

// ---------------- launch ----------------
extern "C" void kernel_launch(void* const* d_in, const int* in_sizes, int n_in,
                              void* d_out, int out_size)
{
    const float* x    = (const float*)d_in[0];
    const float* ln1s = (const float*)d_in[1];
    const float* ln1b = (const float*)d_in[2];
    const float* wqkv = (const float*)d_in[3];
    const float* wout = (const float*)d_in[4];
    const float* bout = (const float*)d_in[5];
    const float* ln2s = (const float*)d_in[6];
    const float* ln2b = (const float*)d_in[7];
    const float* w1   = (const float*)d_in[8];
    const float* b1   = (const float*)d_in[9];
    const float* w2   = (const float*)d_in[10];
    const float* b2   = (const float*)d_in[11];
    float* out = (float*)d_out;

    float *p_xn,*p_qkv,*p_oh,*p_x1,*p_xn2,*p_y;
    float *p_wqkv,*p_wout,*p_w1,*p_w2;
    cudaGetSymbolAddress((void**)&p_xn , g_xn );
    cudaGetSymbolAddress((void**)&p_qkv, g_qkv);
    cudaGetSymbolAddress((void**)&p_oh , g_oh );
    cudaGetSymbolAddress((void**)&p_x1 , g_x1 );
    cudaGetSymbolAddress((void**)&p_xn2, g_xn2);
    cudaGetSymbolAddress((void**)&p_y  , g_y  );
    cudaGetSymbolAddress((void**)&p_wqkv, g_wqkv);
    cudaGetSymbolAddress((void**)&p_wout, g_wout);
    cudaGetSymbolAddress((void**)&p_w1  , g_w1  );
    cudaGetSymbolAddress((void**)&p_w2  , g_w2  );

    const int attn_smem = 3*64*ATS*sizeof(float);
    cudaFuncSetAttribute(attn_tc_kernel, cudaFuncAttributeMaxDynamicSharedMemorySize, attn_smem);
    const int gemm_smem = (NSTG*128*AS_STRIDE + NSTG*16*BS_STRIDE)*sizeof(float);  // 56832
    cudaFuncSetAttribute(tgemm_kernel<0>, cudaFuncAttributeMaxDynamicSharedMemorySize, gemm_smem);
    cudaFuncSetAttribute(tgemm_kernel<1>, cudaFuncAttributeMaxDynamicSharedMemorySize, gemm_smem);
    cudaFuncSetAttribute(tgemm_kernel<2>, cudaFuncAttributeMaxDynamicSharedMemorySize, gemm_smem);

    // round weights to tf32
    round_kernel<<<(DD*3*DD/4+255)/256,256>>>(wqkv, p_wqkv, DD*3*DD/4);
    round_kernel<<<(DD*DD/4+255)/256,256>>>(wout, p_wout, DD*DD/4);
    round_kernel<<<(DD*2*DD/4+255)/256,256>>>(w1, p_w1, DD*2*DD/4);
    round_kernel<<<(2*DD*DD/4+255)/256,256>>>(w2, p_w2, 2*DD*DD/4);

    ln_kernel<<<MM,256>>>(x, ln1s, ln1b, p_xn);
    tgemm_kernel<0><<<dim3(3*DD/128, MM/128),256,gemm_smem>>>(p_xn, p_wqkv, p_qkv, MM, 3*DD, DD, nullptr, nullptr);
    attn_tc_kernel<<<dim3(NSEQ/64, BB*NH),128,attn_smem>>>(p_qkv, p_oh);
    tgemm_kernel<1><<<dim3(DD/128, MM/128),256,gemm_smem>>>(p_oh, p_wout, p_x1, MM, DD, DD, bout, x);
    ln_kernel<<<MM,256>>>(p_x1, ln2s, ln2b, p_xn2);
    tgemm_kernel<2><<<dim3(2*DD/128, MM/128),256,gemm_smem>>>(p_xn2, p_w1, p_y, MM, 2*DD, DD, b1, nullptr);
    tgemm_kernel<1><<<dim3(DD/128, MM/128),256,gemm_smem>>>(p_y, p_w2, out, MM, DD, 2*DD, b2, p_x1);
}